// round 8
// baseline (speedup 1.0000x reference)
#include <cuda_runtime.h>
#include <cstdint>

#define SH 68                    // smem row stride in floats
#define SZ (64 * SH)             // padded 64x64 matrix (floats)
#define NHEADS 8
#define NMAX 2048
#define MASK56 0x00FFFFFFFFFFFFFFull

// ---------------- device scratch ----------------
__device__ float g_powers[NHEADS][16][4096];     // g_powers[h][k] = B_h^k
__device__ float g_sos[4096];
__device__ int   g_key[NMAX];
__device__ int   g_perm[NMAX];

// packed f32x2 FFMA: acc(row-pair) += a2(row-pair) * (b, b)
#define FFMA2B(acc, a2, b)                                                    \
    asm("{\n\t.reg .b64 t;\n\tmov.b64 t, {%2,%2};\n\t"                        \
        "fma.rn.f32x2 %0, %1, t, %0;\n\t}"                                    \
        : "+l"(acc) : "l"(a2), "f"(b))

__device__ __forceinline__ float f2lo(unsigned long long v) {
    return __uint_as_float((unsigned)(v & 0xffffffffull));
}
__device__ __forceinline__ float f2hi(unsigned long long v) {
    return __uint_as_float((unsigned)(v >> 32));
}

// ---- 64x64 mm core (1024 thr): result = (AT)^T * B.
// acc[c] = packed (C[r0][c0+c], C[r0+1][c0+c]).
// Per j: 1 LDS.64 (A row-pair, contiguous in AT) + 1 LDS.64 (B col-pair)
//        + 2 MOV.b64 + 2 FFMA2.
__device__ __forceinline__ void mm_acc(const float* __restrict__ AT,
                                       const float* __restrict__ B,
                                       unsigned long long acc[2],
                                       int r0, int c0) {
    const float* ap = AT + r0;
    const float* bp = B + c0;
    acc[0] = 0ull; acc[1] = 0ull;
#pragma unroll 8
    for (int j = 0; j < 64; j++) {
        unsigned long long a2 = *(const unsigned long long*)(ap + j * SH);
        float2 bb = *(const float2*)(bp + j * SH);
        FFMA2B(acc[0], a2, bb.x);
        FFMA2B(acc[1], a2, bb.y);
    }
}

// =================== kernel A: prepare + grouping ===================
// b 0..79 : expm(k*H_h)  (h = b/10, k = b%10 + 1)   [deg-9 PS, 4 matmuls]
// b 80    : expm(H_sos)
// b 81    : grouping (key + perm for maps)
__global__ void __launch_bounds__(1024, 1)
kernelA(const float* __restrict__ raw, const int* __restrict__ pw, int L) {
    extern __shared__ float sm[];
    int b = blockIdx.x;
    int tid = threadIdx.x;

    if (b == 81) {   // ---------------- grouping ----------------
        int* cnt = (int*)sm;
        int* off = cnt + 32;
        if (tid < 20) cnt[tid] = 0;
        __syncthreads();
        for (int n = tid; n < NMAX; n += 1024) {
            const int* p = pw + (size_t)n * L;
            int c = 0;
            for (int t = 0; t < L; t++) c += (p[t] == 1);
            int key = (p[0] == -1) ? 100 : c;
            g_key[n] = key;
            atomicAdd(&cnt[(key == 100) ? 16 : key], 1);
        }
        __syncthreads();
        if (tid == 0) { int s = 0; for (int q = 0; q < 20; q++) { off[q] = s; s += cnt[q]; } }
        __syncthreads();
        for (int n = tid; n < NMAX; n += 1024) {
            int key = g_key[n];
            int pos = atomicAdd(&off[(key == 100) ? 16 : key], 1);
            g_perm[pos] = n;
        }
        return;
    }

    // ---------------- prepare: B_h^k = expm(k*H_h), deg-9 PS --------------
    int h, kk;
    const float* A;
    if (b == 80) { h = -1; kk = 1; A = raw + (size_t)16 * 4096; }
    else         { h = b / 10; kk = b % 10 + 1; A = raw + (size_t)(8 + h) * 4096; }

    float* M  = sm + 0 * SZ;
    float* P2 = sm + 1 * SZ;
    float* P3 = sm + 2 * SZ;
    float* W  = sm + 3 * SZ;

    // 32 warps; warp tile rows [8*(w>>2), +8), cols [16*(w&3), +16)
    int w = tid >> 5, l = tid & 31;
    int r0 = (w >> 2) * 8 + (l >> 3) * 2;
    int c0 = (w & 3) * 16 + (l & 7) * 2;

    float scale = (float)kk * (1.0f / 64.0f);
    for (int i = tid; i < 4096; i += 1024) {
        int rr = i >> 6, cc = i & 63;
        M[rr * SH + cc] = (A[rr * 64 + cc] - A[cc * 64 + rr]) * scale;
    }
    __syncthreads();

    unsigned long long acc[2];

    // P2 = M*M = -(Mt*M)
    mm_acc(M, M, acc, r0, c0);
    *(float2*)(P2 + r0 * SH + c0)       = make_float2(-f2lo(acc[0]), -f2lo(acc[1]));
    *(float2*)(P2 + (r0 + 1) * SH + c0) = make_float2(-f2hi(acc[0]), -f2hi(acc[1]));
    __syncthreads();

    // P3 = M*P2 = -(Mt*P2); fused W = B2 = I/720 + M/5040 + P2/40320 + P3/362880
    mm_acc(M, P2, acc, r0, c0);
#pragma unroll
    for (int i = 0; i < 2; i++) {
        int r = r0 + i;
        float p3x = i ? -f2hi(acc[0]) : -f2lo(acc[0]);
        float p3y = i ? -f2hi(acc[1]) : -f2lo(acc[1]);
        *(float2*)(P3 + r * SH + c0) = make_float2(p3x, p3y);
        float2 mv  = *(const float2*)(M  + r * SH + c0);
        float2 p2v = *(const float2*)(P2 + r * SH + c0);
        float d0 = (r == c0)     ? 1.f : 0.f;
        float d1 = (r == c0 + 1) ? 1.f : 0.f;
        float2 wv;
        wv.x = 1.38888889e-3f * d0 + 1.98412698e-4f * mv.x
             + 2.48015873e-5f * p2v.x + 2.75573192e-6f * p3x;
        wv.y = 1.38888889e-3f * d1 + 1.98412698e-4f * mv.y
             + 2.48015873e-5f * p2v.y + 2.75573192e-6f * p3y;
        *(float2*)(W + r * SH + c0) = wv;
    }
    __syncthreads();

    // T1 = B1 + P3*W = B1 - (P3t*W);  B1 = I/6 + M/24 + P2/120
    mm_acc(P3, W, acc, r0, c0);
    __syncthreads();                         // all reads of W done before overwrite
#pragma unroll
    for (int i = 0; i < 2; i++) {
        int r = r0 + i;
        float px = i ? f2hi(acc[0]) : f2lo(acc[0]);
        float py = i ? f2hi(acc[1]) : f2lo(acc[1]);
        float2 mv  = *(const float2*)(M  + r * SH + c0);
        float2 p2v = *(const float2*)(P2 + r * SH + c0);
        float d0 = (r == c0)     ? 1.f : 0.f;
        float d1 = (r == c0 + 1) ? 1.f : 0.f;
        float2 wv;
        wv.x = (1.f / 6.f) * d0 + (1.f / 24.f) * mv.x + (1.f / 120.f) * p2v.x - px;
        wv.y = (1.f / 6.f) * d1 + (1.f / 24.f) * mv.y + (1.f / 120.f) * p2v.y - py;
        *(float2*)(W + r * SH + c0) = wv;
    }
    __syncthreads();

    // E = B0 + P3*T1 = B0 - (P3t*T1);  B0 = I + M + P2/2
    mm_acc(P3, W, acc, r0, c0);
    float* dst = (h < 0) ? g_sos : g_powers[h][kk];
#pragma unroll
    for (int i = 0; i < 2; i++) {
        int r = r0 + i;
        float px = i ? f2hi(acc[0]) : f2lo(acc[0]);
        float py = i ? f2hi(acc[1]) : f2lo(acc[1]);
        float2 mv  = *(const float2*)(M  + r * SH + c0);
        float2 p2v = *(const float2*)(P2 + r * SH + c0);
        float d0 = (r == c0)     ? 1.f : 0.f;
        float d1 = (r == c0 + 1) ? 1.f : 0.f;
        float ex = d0 + mv.x + 0.5f * p2v.x - px;
        float ey = d1 + mv.y + 0.5f * p2v.y - py;
        *(float2*)(dst + r * 64 + c0) = make_float2(ex, ey);
        if (h >= 0 && kk == 1)    // publish identity as power 0 once per head
            *(float2*)(g_powers[h][0] + r * 64 + c0) = make_float2(d0, d1);
    }
}

// ============ kernel B: maps (256 MB) + steps (16 MB), 256 thr ============
// b 0..2047   : maps gather-broadcast
// b 2048..2303: steps, 8 rows per block (self-contained packing)
__global__ void __launch_bounds__(256)
output_kernel(float4* __restrict__ out, const int* __restrict__ pw, int L,
              float* __restrict__ steps_out, int has_steps) {
    __shared__ unsigned long long tbl[2048];     // 16 KB (steps branch only)
    int b = blockIdx.x;
    int t = threadIdx.x;

    if (b < 2048) {          // ---------------- maps ----------------
        int h = b & 7;
        int base = (b >> 3) << 3;
        float4 v0, v1, v2, v3;
        int cached = -12345;
#pragma unroll 1
        for (int e = 0; e < 8; e++) {
            int n = g_perm[base + e];
            int key = g_key[n];
            if (key != cached) {
                const float4* src = (key == 100) ? (const float4*)g_sos
                                                 : (const float4*)g_powers[h][key];
                v0 = src[t]; v1 = src[t + 256]; v2 = src[t + 512]; v3 = src[t + 768];
                cached = key;
            }
            float4* dst = out + ((size_t)((unsigned)(n * NHEADS + h)) << 10);
            __stcs(dst + t,       v0);
            __stcs(dst + t + 256, v1);
            __stcs(dst + t + 512, v2);
            __stcs(dst + t + 768, v3);
        }
        return;
    }

    // ---------------- steps ----------------
    if (!has_steps) return;
#pragma unroll
    for (int q = 0; q < 8; q++) {
        int n = t + q * 256;
        const int* p = pw + (size_t)n * L;
        unsigned long long pack = 0ull;
        int len = 0;
        for (int s = 0; s < L; s++) {
            int wv = p[s];
            int code = (wv == -1) ? 0 : wv;
            pack |= ((unsigned long long)(code & 3)) << (2 * s);
            if (wv != 3) len++;              // PAD = 3
        }
        tbl[n] = pack | ((unsigned long long)len << 56);
    }
    __syncthreads();

    int i0 = (b - 2048) << 3;
    int j0 = t << 3;
    unsigned long long pj[8];
#pragma unroll
    for (int q = 0; q < 8; q++) pj[q] = tbl[j0 + q];
#pragma unroll
    for (int rr = 0; rr < 8; rr++) {
        int i = i0 + rr;
        unsigned long long pi = tbl[i];
        int li = (int)(pi >> 56);
        float v[8];
#pragma unroll
        for (int q = 0; q < 8; q++) {
            unsigned long long pjq = pj[q];
            int lj = (int)(pjq >> 56);
            unsigned long long d = (pi ^ pjq) & MASK56;
            int pos = d ? ((__ffsll((long long)d) - 1) >> 1) : 64;
            int mn = min(li, lj), mx = max(li, lj);
            v[q] = (float)(mx - min(pos, mn));
        }
        float4* row = (float4*)(steps_out + (size_t)i * NMAX + j0);
        __stcs(row,     make_float4(v[0], v[1], v[2], v[3]));
        __stcs(row + 1, make_float4(v[4], v[5], v[6], v[7]));
    }
}

// ---------------- launch --------------------------------------------------
extern "C" void kernel_launch(void* const* d_in, const int* in_sizes, int n_in,
                              void* d_out, int out_size) {
    const float* raw = (const float*)d_in[0];
    const int*   pw  = (const int*)d_in[1];
    const int L = in_sizes[1] / NMAX;
    float* out = (float*)d_out;

    size_t maps_elems = (size_t)NMAX * NHEADS * 4096;
    int has_steps = ((size_t)out_size >= maps_elems + (size_t)NMAX * NMAX) ? 1 : 0;

    size_t smem = 4ull * SZ * sizeof(float);   // 69632 B
    cudaFuncSetAttribute(kernelA, cudaFuncAttributeMaxDynamicSharedMemorySize,
                         (int)smem);

    kernelA<<<82, 1024, smem>>>(raw, pw, L);
    output_kernel<<<2048 + 256, 256>>>((float4*)out, pw, L,
                                       out + maps_elems, has_steps);
}

// round 9
// speedup vs baseline: 1.0480x; 1.0480x over previous
#include <cuda_runtime.h>
#include <cstdint>

#define SH 68                    // smem row stride in floats
#define SZ (64 * SH)             // padded 64x64 matrix (floats)
#define NHEADS 8
#define NMAX 2048
#define MASK56 0x00FFFFFFFFFFFFFFull

// ---------------- device scratch ----------------
__device__ float g_powers[NHEADS][16][4096];     // g_powers[h][k] = B_h^k
__device__ float g_sos[4096];
__device__ int   g_key[NMAX];
__device__ int   g_perm[NMAX];

// packed f32x2 FFMA: acc(row-pair) += a2(row-pair) * (b, b)
#define FFMA2B(acc, a2, b)                                                    \
    asm("{\n\t.reg .b64 t;\n\tmov.b64 t, {%2,%2};\n\t"                        \
        "fma.rn.f32x2 %0, %1, t, %0;\n\t}"                                    \
        : "+l"(acc) : "l"(a2), "f"(b))

__device__ __forceinline__ float f2lo(unsigned long long v) {
    return __uint_as_float((unsigned)(v & 0xffffffffull));
}
__device__ __forceinline__ float f2hi(unsigned long long v) {
    return __uint_as_float((unsigned)(v >> 32));
}

// ---- 64x64 mm core (1024 thr): result = (AT)^T * B.
// acc[c] = packed (C[r0][c0+c], C[r0+1][c0+c]).
__device__ __forceinline__ void mm_acc(const float* __restrict__ AT,
                                       const float* __restrict__ B,
                                       unsigned long long acc[2],
                                       int r0, int c0) {
    const float* ap = AT + r0;
    const float* bp = B + c0;
    acc[0] = 0ull; acc[1] = 0ull;
#pragma unroll 8
    for (int j = 0; j < 64; j++) {
        unsigned long long a2 = *(const unsigned long long*)(ap + j * SH);
        float2 bb = *(const float2*)(bp + j * SH);
        FFMA2B(acc[0], a2, bb.x);
        FFMA2B(acc[1], a2, bb.y);
    }
}

// =================== kernel A: prepare + grouping + steps ===================
// b 0..79  : expm(k*H_h)  (h = b/10, k = b%10 + 1)   [deg-9 PS, 4 matmuls]
// b 80     : expm(H_sos)
// b 81     : grouping (key + perm for maps)
// b 82..337: steps, 8 rows per block (self-contained; hidden under prepare)
__global__ void __launch_bounds__(1024, 1)
kernelA(const float* __restrict__ raw, const int* __restrict__ pw, int L,
        float* __restrict__ steps_out, int has_steps) {
    extern __shared__ float sm[];
    int b = blockIdx.x;
    int tid = threadIdx.x;

    if (b >= 82) {   // ---------------- steps ----------------
        if (!has_steps) return;
        unsigned long long* tbl = (unsigned long long*)sm;   // 16 KB of dynamic
#pragma unroll
        for (int q = 0; q < 2; q++) {
            int n = (tid << 1) + q;
            const int* p = pw + (size_t)n * L;
            unsigned long long pack = 0ull;
            int len = 0;
            for (int t = 0; t < L; t++) {
                int wv = p[t];
                int code = (wv == -1) ? 0 : wv;
                pack |= ((unsigned long long)(code & 3)) << (2 * t);
                if (wv != 3) len++;                  // PAD = 3
            }
            tbl[n] = pack | ((unsigned long long)len << 56);
        }
        __syncthreads();
        int i0 = ((b - 82) << 3) + ((tid >> 9) << 2);    // 4 rows per half-block
        int j0 = (tid & 511) << 2;
        unsigned long long pj0 = tbl[j0], pj1 = tbl[j0 + 1];
        unsigned long long pj2 = tbl[j0 + 2], pj3 = tbl[j0 + 3];
#pragma unroll
        for (int rr = 0; rr < 4; rr++) {
            int i = i0 + rr;
            unsigned long long pi = tbl[i];
            int li = (int)(pi >> 56);
            unsigned long long pjs[4] = {pj0, pj1, pj2, pj3};
            float v[4];
#pragma unroll
            for (int q = 0; q < 4; q++) {
                unsigned long long pj = pjs[q];
                int lj = (int)(pj >> 56);
                unsigned long long d = (pi ^ pj) & MASK56;
                int pos = d ? ((__ffsll((long long)d) - 1) >> 1) : 64;
                int mn = min(li, lj), mx = max(li, lj);
                v[q] = (float)(mx - min(pos, mn));
            }
            __stcs((float4*)(steps_out + (size_t)i * NMAX + j0),
                   make_float4(v[0], v[1], v[2], v[3]));
        }
        return;
    }

    if (b == 81) {   // ---------------- grouping ----------------
        int* cnt = (int*)sm;
        int* off = cnt + 32;
        if (tid < 20) cnt[tid] = 0;
        __syncthreads();
        for (int n = tid; n < NMAX; n += 1024) {
            const int* p = pw + (size_t)n * L;
            int c = 0;
            for (int t = 0; t < L; t++) c += (p[t] == 1);
            int key = (p[0] == -1) ? 100 : c;
            g_key[n] = key;
            atomicAdd(&cnt[(key == 100) ? 16 : key], 1);
        }
        __syncthreads();
        if (tid == 0) { int s = 0; for (int q = 0; q < 20; q++) { off[q] = s; s += cnt[q]; } }
        __syncthreads();
        for (int n = tid; n < NMAX; n += 1024) {
            int key = g_key[n];
            int pos = atomicAdd(&off[(key == 100) ? 16 : key], 1);
            g_perm[pos] = n;
        }
        return;
    }

    // ---------------- prepare: B_h^k = expm(k*H_h), deg-9 PS --------------
    int h, kk;
    const float* A;
    if (b == 80) { h = -1; kk = 1; A = raw + (size_t)16 * 4096; }
    else         { h = b / 10; kk = b % 10 + 1; A = raw + (size_t)(8 + h) * 4096; }

    float* M  = sm + 0 * SZ;
    float* P2 = sm + 1 * SZ;
    float* P3 = sm + 2 * SZ;
    float* W  = sm + 3 * SZ;

    int w = tid >> 5, l = tid & 31;
    int r0 = (w >> 2) * 8 + (l >> 3) * 2;
    int c0 = (w & 3) * 16 + (l & 7) * 2;

    float scale = (float)kk * (1.0f / 64.0f);
    for (int i = tid; i < 4096; i += 1024) {
        int rr = i >> 6, cc = i & 63;
        M[rr * SH + cc] = (A[rr * 64 + cc] - A[cc * 64 + rr]) * scale;
    }
    __syncthreads();

    unsigned long long acc[2];

    // P2 = M*M = -(Mt*M)
    mm_acc(M, M, acc, r0, c0);
    *(float2*)(P2 + r0 * SH + c0)       = make_float2(-f2lo(acc[0]), -f2lo(acc[1]));
    *(float2*)(P2 + (r0 + 1) * SH + c0) = make_float2(-f2hi(acc[0]), -f2hi(acc[1]));
    __syncthreads();

    // P3 = M*P2 = -(Mt*P2); fused W = B2 = I/720 + M/5040 + P2/40320 + P3/362880
    mm_acc(M, P2, acc, r0, c0);
#pragma unroll
    for (int i = 0; i < 2; i++) {
        int r = r0 + i;
        float p3x = i ? -f2hi(acc[0]) : -f2lo(acc[0]);
        float p3y = i ? -f2hi(acc[1]) : -f2lo(acc[1]);
        *(float2*)(P3 + r * SH + c0) = make_float2(p3x, p3y);
        float2 mv  = *(const float2*)(M  + r * SH + c0);
        float2 p2v = *(const float2*)(P2 + r * SH + c0);
        float d0 = (r == c0)     ? 1.f : 0.f;
        float d1 = (r == c0 + 1) ? 1.f : 0.f;
        float2 wv;
        wv.x = 1.38888889e-3f * d0 + 1.98412698e-4f * mv.x
             + 2.48015873e-5f * p2v.x + 2.75573192e-6f * p3x;
        wv.y = 1.38888889e-3f * d1 + 1.98412698e-4f * mv.y
             + 2.48015873e-5f * p2v.y + 2.75573192e-6f * p3y;
        *(float2*)(W + r * SH + c0) = wv;
    }
    __syncthreads();

    // T1 = B1 + P3*W = B1 - (P3t*W);  B1 = I/6 + M/24 + P2/120
    mm_acc(P3, W, acc, r0, c0);
    __syncthreads();                         // all reads of W done before overwrite
#pragma unroll
    for (int i = 0; i < 2; i++) {
        int r = r0 + i;
        float px = i ? f2hi(acc[0]) : f2lo(acc[0]);
        float py = i ? f2hi(acc[1]) : f2lo(acc[1]);
        float2 mv  = *(const float2*)(M  + r * SH + c0);
        float2 p2v = *(const float2*)(P2 + r * SH + c0);
        float d0 = (r == c0)     ? 1.f : 0.f;
        float d1 = (r == c0 + 1) ? 1.f : 0.f;
        float2 wv;
        wv.x = (1.f / 6.f) * d0 + (1.f / 24.f) * mv.x + (1.f / 120.f) * p2v.x - px;
        wv.y = (1.f / 6.f) * d1 + (1.f / 24.f) * mv.y + (1.f / 120.f) * p2v.y - py;
        *(float2*)(W + r * SH + c0) = wv;
    }
    __syncthreads();

    // E = B0 + P3*T1 = B0 - (P3t*T1);  B0 = I + M + P2/2
    mm_acc(P3, W, acc, r0, c0);
    float* dst = (h < 0) ? g_sos : g_powers[h][kk];
#pragma unroll
    for (int i = 0; i < 2; i++) {
        int r = r0 + i;
        float px = i ? f2hi(acc[0]) : f2lo(acc[0]);
        float py = i ? f2hi(acc[1]) : f2lo(acc[1]);
        float2 mv  = *(const float2*)(M  + r * SH + c0);
        float2 p2v = *(const float2*)(P2 + r * SH + c0);
        float d0 = (r == c0)     ? 1.f : 0.f;
        float d1 = (r == c0 + 1) ? 1.f : 0.f;
        float ex = d0 + mv.x + 0.5f * p2v.x - px;
        float ey = d1 + mv.y + 0.5f * p2v.y - py;
        *(float2*)(dst + r * 64 + c0) = make_float2(ex, ey);
        if (h >= 0 && kk == 1)    // publish identity as power 0 once per head
            *(float2*)(g_powers[h][0] + r * 64 + c0) = make_float2(d0, d1);
    }
}

// =================== kernel B: maps gather-broadcast (256 MB) ==============
__global__ void __launch_bounds__(256)
maps_writer(float4* __restrict__ out) {
    int b = blockIdx.x;
    int h = b & 7;
    int base = (b >> 3) << 3;
    int t = threadIdx.x;
    float4 v0, v1, v2, v3;
    int cached = -12345;
#pragma unroll 1
    for (int e = 0; e < 8; e++) {
        int n = g_perm[base + e];
        int key = g_key[n];
        if (key != cached) {
            const float4* src = (key == 100) ? (const float4*)g_sos
                                             : (const float4*)g_powers[h][key];
            v0 = src[t]; v1 = src[t + 256]; v2 = src[t + 512]; v3 = src[t + 768];
            cached = key;
        }
        float4* dst = out + ((size_t)((unsigned)(n * NHEADS + h)) << 10);
        __stcs(dst + t,       v0);
        __stcs(dst + t + 256, v1);
        __stcs(dst + t + 512, v2);
        __stcs(dst + t + 768, v3);
    }
}

// ---------------- launch --------------------------------------------------
extern "C" void kernel_launch(void* const* d_in, const int* in_sizes, int n_in,
                              void* d_out, int out_size) {
    const float* raw = (const float*)d_in[0];
    const int*   pw  = (const int*)d_in[1];
    const int L = in_sizes[1] / NMAX;
    float* out = (float*)d_out;

    size_t maps_elems = (size_t)NMAX * NHEADS * 4096;
    int has_steps = ((size_t)out_size >= maps_elems + (size_t)NMAX * NMAX) ? 1 : 0;

    size_t smem = 4ull * SZ * sizeof(float);   // 69632 B
    cudaFuncSetAttribute(kernelA, cudaFuncAttributeMaxDynamicSharedMemorySize,
                         (int)smem);

    kernelA<<<82 + 256, 1024, smem>>>(raw, pw, L, out + maps_elems, has_steps);
    maps_writer<<<2048, 256>>>((float4*)out);
}

// round 10
// speedup vs baseline: 1.1531x; 1.1004x over previous
#include <cuda_runtime.h>
#include <cstdint>

#define SH 68                    // smem row stride in floats
#define SZ (64 * SH)             // padded 64x64 matrix (floats)
#define NHEADS 8
#define NMAX 2048
#define MASK56 0x00FFFFFFFFFFFFFFull

// ---------------- device scratch ----------------
__device__ float g_powers[NHEADS][16][4096];     // g_powers[h][k] = B_h^k
__device__ float g_sos[4096];
__device__ int   g_key[NMAX];
__device__ int   g_perm[NMAX];

// packed f32x2 FFMA: acc(row-pair) += a2(row-pair) * (b, b)
#define FFMA2B(acc, a2, b)                                                    \
    asm("{\n\t.reg .b64 t;\n\tmov.b64 t, {%2,%2};\n\t"                        \
        "fma.rn.f32x2 %0, %1, t, %0;\n\t}"                                    \
        : "+l"(acc) : "l"(a2), "f"(b))

__device__ __forceinline__ float f2lo(unsigned long long v) {
    return __uint_as_float((unsigned)(v & 0xffffffffull));
}
__device__ __forceinline__ float f2hi(unsigned long long v) {
    return __uint_as_float((unsigned)(v >> 32));
}

// ---- 64x64 mm core (1024 thr): result = (AT)^T * B.
// acc[c] = packed (C[r0][c0+c], C[r0+1][c0+c]).
__device__ __forceinline__ void mm_acc(const float* __restrict__ AT,
                                       const float* __restrict__ B,
                                       unsigned long long acc[2],
                                       int r0, int c0) {
    const float* ap = AT + r0;
    const float* bp = B + c0;
    acc[0] = 0ull; acc[1] = 0ull;
#pragma unroll 8
    for (int j = 0; j < 64; j++) {
        unsigned long long a2 = *(const unsigned long long*)(ap + j * SH);
        float2 bb = *(const float2*)(bp + j * SH);
        FFMA2B(acc[0], a2, bb.x);
        FFMA2B(acc[1], a2, bb.y);
    }
}

// ============ kernel A: prepare + steps + grouping, 146 blocks =============
// Grid fits in the first placement wave (<=148) so every block owns one SM:
//   b 0..79  : expm(k*H_h)  (h = b/10, k = b%10 + 1)   [deg-9 PS, 4 matmuls]
//   b 80     : expm(H_sos)
//   b 81..144: steps, 32 rows per block (hidden under prepare, own SMs)
//   b 145    : grouping (key + perm for maps)
__global__ void __launch_bounds__(1024, 1)
kernelA(const float* __restrict__ raw, const int* __restrict__ pw, int L,
        float* __restrict__ steps_out, int has_steps) {
    extern __shared__ float sm[];
    int b = blockIdx.x;
    int tid = threadIdx.x;

    if (b >= 81 && b <= 144) {   // ---------------- steps ----------------
        if (!has_steps) return;
        unsigned long long* tbl = (unsigned long long*)sm;   // 2048 packs
#pragma unroll
        for (int q = 0; q < 2; q++) {
            int n = (tid << 1) + q;
            const int* p = pw + (size_t)n * L;
            unsigned long long pack = 0ull;
            int len = 0;
            for (int t = 0; t < L; t++) {
                int wv = p[t];
                int code = (wv == -1) ? 0 : wv;
                pack |= ((unsigned long long)(code & 3)) << (2 * t);
                if (wv != 3) len++;                  // PAD = 3
            }
            tbl[n] = pack | ((unsigned long long)len << 56);
        }
        __syncthreads();
        int half = tid >> 9;                         // 0/1: 16 rows each
        int i0 = ((b - 81) << 5) + (half << 4);
        int j0 = (tid & 511) << 2;
        unsigned long long pj0 = tbl[j0], pj1 = tbl[j0 + 1];
        unsigned long long pj2 = tbl[j0 + 2], pj3 = tbl[j0 + 3];
#pragma unroll 4
        for (int rr = 0; rr < 16; rr++) {
            int i = i0 + rr;
            unsigned long long pi = tbl[i];
            int li = (int)(pi >> 56);
            unsigned long long pjs[4] = {pj0, pj1, pj2, pj3};
            float v[4];
#pragma unroll
            for (int q = 0; q < 4; q++) {
                unsigned long long pj = pjs[q];
                int lj = (int)(pj >> 56);
                unsigned long long d = (pi ^ pj) & MASK56;
                int pos = d ? ((__ffsll((long long)d) - 1) >> 1) : 64;
                int mn = min(li, lj), mx = max(li, lj);
                v[q] = (float)(mx - min(pos, mn));
            }
            __stcs((float4*)(steps_out + (size_t)i * NMAX + j0),
                   make_float4(v[0], v[1], v[2], v[3]));
        }
        return;
    }

    if (b == 145) {   // ---------------- grouping ----------------
        int* cnt = (int*)sm;
        int* off = cnt + 32;
        if (tid < 20) cnt[tid] = 0;
        __syncthreads();
        for (int n = tid; n < NMAX; n += 1024) {
            const int* p = pw + (size_t)n * L;
            int c = 0;
            for (int t = 0; t < L; t++) c += (p[t] == 1);
            int key = (p[0] == -1) ? 100 : c;
            g_key[n] = key;
            atomicAdd(&cnt[(key == 100) ? 16 : key], 1);
        }
        __syncthreads();
        if (tid == 0) { int s = 0; for (int q = 0; q < 20; q++) { off[q] = s; s += cnt[q]; } }
        __syncthreads();
        for (int n = tid; n < NMAX; n += 1024) {
            int key = g_key[n];
            int pos = atomicAdd(&off[(key == 100) ? 16 : key], 1);
            g_perm[pos] = n;
        }
        return;
    }

    // ---------------- prepare: B_h^k = expm(k*H_h), deg-9 PS --------------
    int h, kk;
    const float* A;
    if (b == 80) { h = -1; kk = 1; A = raw + (size_t)16 * 4096; }
    else         { h = b / 10; kk = b % 10 + 1; A = raw + (size_t)(8 + h) * 4096; }

    float* M  = sm + 0 * SZ;
    float* P2 = sm + 1 * SZ;
    float* P3 = sm + 2 * SZ;
    float* W  = sm + 3 * SZ;
    float* W2 = sm + 4 * SZ;

    int w = tid >> 5, l = tid & 31;
    int r0 = (w >> 2) * 8 + (l >> 3) * 2;
    int c0 = (w & 3) * 16 + (l & 7) * 2;

    float scale = (float)kk * (1.0f / 64.0f);
    for (int i = tid; i < 4096; i += 1024) {
        int rr = i >> 6, cc = i & 63;
        M[rr * SH + cc] = (A[rr * 64 + cc] - A[cc * 64 + rr]) * scale;
    }
    __syncthreads();

    unsigned long long acc[2];

    // P2 = M*M = -(Mt*M)
    mm_acc(M, M, acc, r0, c0);
    *(float2*)(P2 + r0 * SH + c0)       = make_float2(-f2lo(acc[0]), -f2lo(acc[1]));
    *(float2*)(P2 + (r0 + 1) * SH + c0) = make_float2(-f2hi(acc[0]), -f2hi(acc[1]));
    __syncthreads();

    // P3 = M*P2 = -(Mt*P2); fused W = B2 = I/720 + M/5040 + P2/40320 + P3/362880
    mm_acc(M, P2, acc, r0, c0);
#pragma unroll
    for (int i = 0; i < 2; i++) {
        int r = r0 + i;
        float p3x = i ? -f2hi(acc[0]) : -f2lo(acc[0]);
        float p3y = i ? -f2hi(acc[1]) : -f2lo(acc[1]);
        *(float2*)(P3 + r * SH + c0) = make_float2(p3x, p3y);
        float2 mv  = *(const float2*)(M  + r * SH + c0);
        float2 p2v = *(const float2*)(P2 + r * SH + c0);
        float d0 = (r == c0)     ? 1.f : 0.f;
        float d1 = (r == c0 + 1) ? 1.f : 0.f;
        float2 wv;
        wv.x = 1.38888889e-3f * d0 + 1.98412698e-4f * mv.x
             + 2.48015873e-5f * p2v.x + 2.75573192e-6f * p3x;
        wv.y = 1.38888889e-3f * d1 + 1.98412698e-4f * mv.y
             + 2.48015873e-5f * p2v.y + 2.75573192e-6f * p3y;
        *(float2*)(W + r * SH + c0) = wv;
    }
    __syncthreads();

    // T1 = B1 + P3*W = B1 - (P3t*W) -> W2 (no drain sync needed: W untouched)
    mm_acc(P3, W, acc, r0, c0);
#pragma unroll
    for (int i = 0; i < 2; i++) {
        int r = r0 + i;
        float px = i ? f2hi(acc[0]) : f2lo(acc[0]);
        float py = i ? f2hi(acc[1]) : f2lo(acc[1]);
        float2 mv  = *(const float2*)(M  + r * SH + c0);
        float2 p2v = *(const float2*)(P2 + r * SH + c0);
        float d0 = (r == c0)     ? 1.f : 0.f;
        float d1 = (r == c0 + 1) ? 1.f : 0.f;
        float2 wv;
        wv.x = (1.f / 6.f) * d0 + (1.f / 24.f) * mv.x + (1.f / 120.f) * p2v.x - px;
        wv.y = (1.f / 6.f) * d1 + (1.f / 24.f) * mv.y + (1.f / 120.f) * p2v.y - py;
        *(float2*)(W2 + r * SH + c0) = wv;
    }
    __syncthreads();

    // E = B0 + P3*T1 = B0 - (P3t*W2);  B0 = I + M + P2/2
    mm_acc(P3, W2, acc, r0, c0);
    float* dst = (h < 0) ? g_sos : g_powers[h][kk];
#pragma unroll
    for (int i = 0; i < 2; i++) {
        int r = r0 + i;
        float px = i ? f2hi(acc[0]) : f2lo(acc[0]);
        float py = i ? f2hi(acc[1]) : f2lo(acc[1]);
        float2 mv  = *(const float2*)(M  + r * SH + c0);
        float2 p2v = *(const float2*)(P2 + r * SH + c0);
        float d0 = (r == c0)     ? 1.f : 0.f;
        float d1 = (r == c0 + 1) ? 1.f : 0.f;
        float ex = d0 + mv.x + 0.5f * p2v.x - px;
        float ey = d1 + mv.y + 0.5f * p2v.y - py;
        *(float2*)(dst + r * 64 + c0) = make_float2(ex, ey);
        if (h >= 0 && kk == 1)    // publish identity as power 0 once per head
            *(float2*)(g_powers[h][0] + r * 64 + c0) = make_float2(d0, d1);
    }
}

// =================== kernel B: maps gather-broadcast (256 MB) ==============
__global__ void __launch_bounds__(256)
maps_writer(float4* __restrict__ out) {
    int b = blockIdx.x;
    int h = b & 7;
    int base = (b >> 3) << 3;
    int t = threadIdx.x;
    float4 v0, v1, v2, v3;
    int cached = -12345;
#pragma unroll 1
    for (int e = 0; e < 8; e++) {
        int n = g_perm[base + e];
        int key = g_key[n];
        if (key != cached) {
            const float4* src = (key == 100) ? (const float4*)g_sos
                                             : (const float4*)g_powers[h][key];
            v0 = src[t]; v1 = src[t + 256]; v2 = src[t + 512]; v3 = src[t + 768];
            cached = key;
        }
        float4* dst = out + ((size_t)((unsigned)(n * NHEADS + h)) << 10);
        __stcs(dst + t,       v0);
        __stcs(dst + t + 256, v1);
        __stcs(dst + t + 512, v2);
        __stcs(dst + t + 768, v3);
    }
}

// ---------------- launch --------------------------------------------------
extern "C" void kernel_launch(void* const* d_in, const int* in_sizes, int n_in,
                              void* d_out, int out_size) {
    const float* raw = (const float*)d_in[0];
    const int*   pw  = (const int*)d_in[1];
    const int L = in_sizes[1] / NMAX;
    float* out = (float*)d_out;

    size_t maps_elems = (size_t)NMAX * NHEADS * 4096;
    int has_steps = ((size_t)out_size >= maps_elems + (size_t)NMAX * NMAX) ? 1 : 0;

    size_t smem = 5ull * SZ * sizeof(float);   // 87040 B (5 slots)
    cudaFuncSetAttribute(kernelA, cudaFuncAttributeMaxDynamicSharedMemorySize,
                         (int)smem);

    kernelA<<<146, 1024, smem>>>(raw, pw, L, out + maps_elems, has_steps);
    maps_writer<<<2048, 256>>>((float4*)out);
}

// round 11
// speedup vs baseline: 1.1913x; 1.0331x over previous
#include <cuda_runtime.h>
#include <cstdint>

#define SH 68                    // smem row stride in floats
#define SZ (64 * SH)             // padded 64x64 matrix (floats)
#define NHEADS 8
#define NMAX 2048
#define MASK56 0x00FFFFFFFFFFFFFFull

// ---------------- device scratch ----------------
__device__ float g_powers[NHEADS][16][4096];     // g_powers[h][k] = B_h^k
__device__ float g_sos[4096];
__device__ int   g_key[NMAX];
__device__ int   g_perm[NMAX];

// packed f32x2 FFMA: acc(row-pair) += a2(row-pair) * (b, b)
#define FFMA2B(acc, a2, b)                                                    \
    asm("{\n\t.reg .b64 t;\n\tmov.b64 t, {%2,%2};\n\t"                        \
        "fma.rn.f32x2 %0, %1, t, %0;\n\t}"                                    \
        : "+l"(acc) : "l"(a2), "f"(b))

__device__ __forceinline__ float f2lo(unsigned long long v) {
    return __uint_as_float((unsigned)(v & 0xffffffffull));
}
__device__ __forceinline__ float f2hi(unsigned long long v) {
    return __uint_as_float((unsigned)(v >> 32));
}

// ---- 64x64 mm core (1024 thr): result = (AT)^T * B.
// acc[c] = packed (C[r0][c0+c], C[r0+1][c0+c]).
__device__ __forceinline__ void mm_acc(const float* __restrict__ AT,
                                       const float* __restrict__ B,
                                       unsigned long long acc[2],
                                       int r0, int c0) {
    const float* ap = AT + r0;
    const float* bp = B + c0;
    acc[0] = 0ull; acc[1] = 0ull;
#pragma unroll 8
    for (int j = 0; j < 64; j++) {
        unsigned long long a2 = *(const unsigned long long*)(ap + j * SH);
        float2 bb = *(const float2*)(bp + j * SH);
        FFMA2B(acc[0], a2, bb.x);
        FFMA2B(acc[1], a2, bb.y);
    }
}

// ============ kernel A: prepare + steps + grouping, 146 blocks =============
// Grid fits in the first placement wave (<=148) so every block owns one SM:
//   b 0..79  : expm(k*H_h)  (h = b/10, k = b%10 + 1)   [deg-9 PS, 4 matmuls]
//   b 80     : expm(H_sos)
//   b 81..144: steps, 32 rows per block (hidden under prepare, own SMs)
//   b 145    : grouping (key + perm for maps)
__global__ void __launch_bounds__(1024, 1)
kernelA(const float* __restrict__ raw, const int* __restrict__ pw, int L,
        float* __restrict__ steps_out, int has_steps) {
    extern __shared__ float sm[];
    int b = blockIdx.x;
    int tid = threadIdx.x;

    if (b >= 81 && b <= 144) {   // ---------------- steps ----------------
        if (has_steps) {
            unsigned long long* tbl = (unsigned long long*)sm;   // 2048 packs
#pragma unroll
            for (int q = 0; q < 2; q++) {
                int n = (tid << 1) + q;
                const int* p = pw + (size_t)n * L;
                unsigned long long pack = 0ull;
                int len = 0;
                for (int t = 0; t < L; t++) {
                    int wv = p[t];
                    int code = (wv == -1) ? 0 : wv;
                    pack |= ((unsigned long long)(code & 3)) << (2 * t);
                    if (wv != 3) len++;                  // PAD = 3
                }
                tbl[n] = pack | ((unsigned long long)len << 56);
            }
            __syncthreads();
            int half = tid >> 9;                         // 0/1: 16 rows each
            int i0 = ((b - 81) << 5) + (half << 4);
            int j0 = (tid & 511) << 2;
            unsigned long long pj0 = tbl[j0], pj1 = tbl[j0 + 1];
            unsigned long long pj2 = tbl[j0 + 2], pj3 = tbl[j0 + 3];
#pragma unroll 4
            for (int rr = 0; rr < 16; rr++) {
                int i = i0 + rr;
                unsigned long long pi = tbl[i];
                int li = (int)(pi >> 56);
                unsigned long long pjs[4] = {pj0, pj1, pj2, pj3};
                float v[4];
#pragma unroll
                for (int q = 0; q < 4; q++) {
                    unsigned long long pj = pjs[q];
                    int lj = (int)(pj >> 56);
                    unsigned long long d = (pi ^ pj) & MASK56;
                    int pos = d ? ((__ffsll((long long)d) - 1) >> 1) : 64;
                    int mn = min(li, lj), mx = max(li, lj);
                    v[q] = (float)(mx - min(pos, mn));
                }
                __stcs((float4*)(steps_out + (size_t)i * NMAX + j0),
                       make_float4(v[0], v[1], v[2], v[3]));
            }
        }
        cudaTriggerProgrammaticLaunchCompletion();
        return;
    }

    if (b == 145) {   // ---------------- grouping ----------------
        int* cnt = (int*)sm;
        int* off = cnt + 32;
        if (tid < 20) cnt[tid] = 0;
        __syncthreads();
        for (int n = tid; n < NMAX; n += 1024) {
            const int* p = pw + (size_t)n * L;
            int c = 0;
            for (int t = 0; t < L; t++) c += (p[t] == 1);
            int key = (p[0] == -1) ? 100 : c;
            g_key[n] = key;
            atomicAdd(&cnt[(key == 100) ? 16 : key], 1);
        }
        __syncthreads();
        if (tid == 0) { int s = 0; for (int q = 0; q < 20; q++) { off[q] = s; s += cnt[q]; } }
        __syncthreads();
        for (int n = tid; n < NMAX; n += 1024) {
            int key = g_key[n];
            int pos = atomicAdd(&off[(key == 100) ? 16 : key], 1);
            g_perm[pos] = n;
        }
        cudaTriggerProgrammaticLaunchCompletion();
        return;
    }

    // ---------------- prepare: B_h^k = expm(k*H_h), deg-9 PS --------------
    int h, kk;
    const float* A;
    if (b == 80) { h = -1; kk = 1; A = raw + (size_t)16 * 4096; }
    else         { h = b / 10; kk = b % 10 + 1; A = raw + (size_t)(8 + h) * 4096; }

    float* M  = sm + 0 * SZ;
    float* P2 = sm + 1 * SZ;
    float* P3 = sm + 2 * SZ;
    float* W  = sm + 3 * SZ;
    float* W2 = sm + 4 * SZ;

    int w = tid >> 5, l = tid & 31;
    int r0 = (w >> 2) * 8 + (l >> 3) * 2;
    int c0 = (w & 3) * 16 + (l & 7) * 2;

    // Stage A into smem coalesced (1 LDG.128/thread), then build M from smem.
    {
        int rr = tid >> 4;                 // 64 rows, 16 threads per row
        int cc0 = (tid & 15) << 2;
        float4 av = *(const float4*)(A + rr * 64 + cc0);
        *(float4*)(W + rr * SH + cc0) = av;
    }
    __syncthreads();
    float scale = (float)kk * (1.0f / 64.0f);
    for (int i = tid; i < 4096; i += 1024) {
        int rr = i >> 6, cc = i & 63;
        M[rr * SH + cc] = (W[rr * SH + cc] - W[cc * SH + rr]) * scale;
    }
    __syncthreads();

    unsigned long long acc[2];

    // P2 = M*M = -(Mt*M)
    mm_acc(M, M, acc, r0, c0);
    *(float2*)(P2 + r0 * SH + c0)       = make_float2(-f2lo(acc[0]), -f2lo(acc[1]));
    *(float2*)(P2 + (r0 + 1) * SH + c0) = make_float2(-f2hi(acc[0]), -f2hi(acc[1]));
    __syncthreads();

    // P3 = M*P2 = -(Mt*P2); fused W = B2 = I/720 + M/5040 + P2/40320 + P3/362880
    mm_acc(M, P2, acc, r0, c0);
    __syncthreads();                       // A-staging reads of W fully drained
#pragma unroll
    for (int i = 0; i < 2; i++) {
        int r = r0 + i;
        float p3x = i ? -f2hi(acc[0]) : -f2lo(acc[0]);
        float p3y = i ? -f2hi(acc[1]) : -f2lo(acc[1]);
        *(float2*)(P3 + r * SH + c0) = make_float2(p3x, p3y);
        float2 mv  = *(const float2*)(M  + r * SH + c0);
        float2 p2v = *(const float2*)(P2 + r * SH + c0);
        float d0 = (r == c0)     ? 1.f : 0.f;
        float d1 = (r == c0 + 1) ? 1.f : 0.f;
        float2 wv;
        wv.x = 1.38888889e-3f * d0 + 1.98412698e-4f * mv.x
             + 2.48015873e-5f * p2v.x + 2.75573192e-6f * p3x;
        wv.y = 1.38888889e-3f * d1 + 1.98412698e-4f * mv.y
             + 2.48015873e-5f * p2v.y + 2.75573192e-6f * p3y;
        *(float2*)(W + r * SH + c0) = wv;
    }
    __syncthreads();

    // T1 = B1 + P3*W = B1 - (P3t*W) -> W2
    mm_acc(P3, W, acc, r0, c0);
#pragma unroll
    for (int i = 0; i < 2; i++) {
        int r = r0 + i;
        float px = i ? f2hi(acc[0]) : f2lo(acc[0]);
        float py = i ? f2hi(acc[1]) : f2lo(acc[1]);
        float2 mv  = *(const float2*)(M  + r * SH + c0);
        float2 p2v = *(const float2*)(P2 + r * SH + c0);
        float d0 = (r == c0)     ? 1.f : 0.f;
        float d1 = (r == c0 + 1) ? 1.f : 0.f;
        float2 wv;
        wv.x = (1.f / 6.f) * d0 + (1.f / 24.f) * mv.x + (1.f / 120.f) * p2v.x - px;
        wv.y = (1.f / 6.f) * d1 + (1.f / 24.f) * mv.y + (1.f / 120.f) * p2v.y - py;
        *(float2*)(W2 + r * SH + c0) = wv;
    }
    __syncthreads();

    // E = B0 + P3*T1 = B0 - (P3t*W2);  B0 = I + M + P2/2
    mm_acc(P3, W2, acc, r0, c0);
    float* dst = (h < 0) ? g_sos : g_powers[h][kk];
#pragma unroll
    for (int i = 0; i < 2; i++) {
        int r = r0 + i;
        float px = i ? f2hi(acc[0]) : f2lo(acc[0]);
        float py = i ? f2hi(acc[1]) : f2lo(acc[1]);
        float2 mv  = *(const float2*)(M  + r * SH + c0);
        float2 p2v = *(const float2*)(P2 + r * SH + c0);
        float d0 = (r == c0)     ? 1.f : 0.f;
        float d1 = (r == c0 + 1) ? 1.f : 0.f;
        float ex = d0 + mv.x + 0.5f * p2v.x - px;
        float ey = d1 + mv.y + 0.5f * p2v.y - py;
        *(float2*)(dst + r * 64 + c0) = make_float2(ex, ey);
        if (h >= 0 && kk == 1)    // publish identity as power 0 once per head
            *(float2*)(g_powers[h][0] + r * 64 + c0) = make_float2(d0, d1);
    }
    cudaTriggerProgrammaticLaunchCompletion();
}

// =================== kernel B: maps gather-broadcast (256 MB) ==============
__global__ void __launch_bounds__(256)
maps_writer(float4* __restrict__ out) {
    cudaGridDependencySynchronize();       // PDL: wait for kernelA's writes
    int b = blockIdx.x;
    int h = b & 7;
    int base = (b >> 3) << 3;
    int t = threadIdx.x;
    float4 v0, v1, v2, v3;
    int cached = -12345;
#pragma unroll 1
    for (int e = 0; e < 8; e++) {
        int n = g_perm[base + e];
        int key = g_key[n];
        if (key != cached) {
            const float4* src = (key == 100) ? (const float4*)g_sos
                                             : (const float4*)g_powers[h][key];
            v0 = src[t]; v1 = src[t + 256]; v2 = src[t + 512]; v3 = src[t + 768];
            cached = key;
        }
        float4* dst = out + ((size_t)((unsigned)(n * NHEADS + h)) << 10);
        __stcs(dst + t,       v0);
        __stcs(dst + t + 256, v1);
        __stcs(dst + t + 512, v2);
        __stcs(dst + t + 768, v3);
    }
}

// ---------------- launch --------------------------------------------------
extern "C" void kernel_launch(void* const* d_in, const int* in_sizes, int n_in,
                              void* d_out, int out_size) {
    const float* raw = (const float*)d_in[0];
    const int*   pw  = (const int*)d_in[1];
    const int L = in_sizes[1] / NMAX;
    float* out = (float*)d_out;

    size_t maps_elems = (size_t)NMAX * NHEADS * 4096;
    int has_steps = ((size_t)out_size >= maps_elems + (size_t)NMAX * NMAX) ? 1 : 0;

    size_t smem = 5ull * SZ * sizeof(float);   // 87040 B (5 slots)
    cudaFuncSetAttribute(kernelA, cudaFuncAttributeMaxDynamicSharedMemorySize,
                         (int)smem);

    kernelA<<<146, 1024, smem>>>(raw, pw, L, out + maps_elems, has_steps);

    // PDL launch: maps_writer may be scheduled while kernelA drains; it gates
    // itself with cudaGridDependencySynchronize().
    cudaLaunchConfig_t cfg = {};
    cfg.gridDim = dim3(2048);
    cfg.blockDim = dim3(256);
    cfg.dynamicSmemBytes = 0;
    cfg.stream = 0;
    cudaLaunchAttribute attrs[1];
    attrs[0].id = cudaLaunchAttributeProgrammaticStreamSerialization;
    attrs[0].val.programmaticStreamSerializationAllowed = 1;
    cfg.attrs = attrs;
    cfg.numAttrs = 1;
    cudaLaunchKernelEx(&cfg, maps_writer, (float4*)out);
}